// round 7
// baseline (speedup 1.0000x reference)
#include <cuda_runtime.h>

// Range_Fourier_Net: y = DFT_512(x) per row, complex, output stacked (re, im).
// Radix-8^3 FFT, exact twiddles generated from row 1 of the DFT weight matrix.
//
// R7 = R4 (best: two rows per 64-thread group, conflict-free smem exchanges,
// named group barriers) with __launch_bounds__(256,4): regs fit exactly 64,
// smem 37KB*4=148KB, so 4 CTAs/SM -> 32 warps -> +33% bytes in flight.

#define GROUPS 4
#define CTA_THREADS (GROUPS * 64)
#define BUF_LEN 576   // >= 7*72+63+1 and >= 7*68+63+1

__device__ __forceinline__ float2 cadd(float2 a, float2 b) {
    return make_float2(a.x + b.x, a.y + b.y);
}
__device__ __forceinline__ float2 csub(float2 a, float2 b) {
    return make_float2(a.x - b.x, a.y - b.y);
}
__device__ __forceinline__ float2 cmul(float2 a, float2 b) {
    return make_float2(fmaf(a.x, b.x, -a.y * b.y), fmaf(a.x, b.y, a.y * b.x));
}
// multiply by -i  (W8^2)
__device__ __forceinline__ float2 mul_mi(float2 a) { return make_float2(a.y, -a.x); }

// Natural-order 8-point DFT: v[h] = sum_j v_in[j] * W8^{j*h}, W8 = exp(-i*pi/4)
__device__ __forceinline__ void dft8(float2 v[8]) {
    float2 e0 = v[0], e1 = v[2], e2 = v[4], e3 = v[6];
    float2 o0 = v[1], o1 = v[3], o2 = v[5], o3 = v[7];
    float2 t0 = cadd(e0, e2), t1 = csub(e0, e2);
    float2 t2 = cadd(e1, e3), t3 = mul_mi(csub(e1, e3));
    float2 E0 = cadd(t0, t2), E2 = csub(t0, t2);
    float2 E1 = cadd(t1, t3), E3 = csub(t1, t3);
    float2 s0 = cadd(o0, o2), s1 = csub(o0, o2);
    float2 s2 = cadd(o1, o3), s3 = mul_mi(csub(o1, o3));
    float2 O0 = cadd(s0, s2), O2 = csub(s0, s2);
    float2 O1 = cadd(s1, s3), O3 = csub(s1, s3);
    const float S = 0.70710678118654752440f;
    float2 W1 = make_float2(S * (O1.x + O1.y), S * (O1.y - O1.x));
    float2 W2 = mul_mi(O2);
    float2 W3 = make_float2(S * (O3.y - O3.x), -S * (O3.x + O3.y));
    v[0] = cadd(E0, O0); v[4] = csub(E0, O0);
    v[1] = cadd(E1, W1); v[5] = csub(E1, W1);
    v[2] = cadd(E2, W2); v[6] = csub(E2, W2);
    v[3] = cadd(E3, W3); v[7] = csub(E3, W3);
}

__device__ __forceinline__ void group_bar(int grp) {
    asm volatile("bar.sync %0, 64;" :: "r"(grp + 1) : "memory");
}

// twiddle chain: v[h] *= base^h for h = 1..7
__device__ __forceinline__ void twiddle_chain(float2 v[8], float2 base) {
    float2 f = base;
    #pragma unroll
    for (int h = 1; h < 8; h++) {
        v[h] = cmul(v[h], f);
        if (h < 7) f = cmul(f, base);
    }
}

__global__ __launch_bounds__(CTA_THREADS, 4)
void fft512_kernel(const float* __restrict__ xre, const float* __restrict__ xim,
                   const float* __restrict__ wre, const float* __restrict__ wim,
                   float2* __restrict__ out, int nrows)
{
    // per group: buffers for row A and row B, re/im separate
    __shared__ float bufAre[GROUPS][BUF_LEN], bufAim[GROUPS][BUF_LEN];
    __shared__ float bufBre[GROUPS][BUF_LEN], bufBim[GROUPS][BUF_LEN];

    const int tid = threadIdx.x;
    const int grp = tid >> 6;      // group within CTA
    const int t   = tid & 63;      // 0..63
    const int j0  = t & 7;
    const int h2s = t >> 3;
    const int rowA = (blockIdx.x * GROUPS + grp) * 2;
    const int rowB = rowA + 1;
    const bool actA = rowA < nrows;
    const bool actB = rowB < nrows;

    // Per-thread exact base twiddles from DFT-matrix row 1: W512^m = w[512+m]
    const float2 base1 = make_float2(__ldg(&wre[512 + t]),      __ldg(&wim[512 + t]));
    const float2 base2 = make_float2(__ldg(&wre[512 + 8 * j0]), __ldg(&wim[512 + 8 * j0]));

    // ---- front-batched loads: 32 LDGs in flight ----
    float2 a[8], b[8];
    {
        const float* xrA = xre + (size_t)rowA * 512;
        const float* xiA = xim + (size_t)rowA * 512;
        const float* xrB = xre + (size_t)rowB * 512;
        const float* xiB = xim + (size_t)rowB * 512;
        float arv[8], aiv[8], brv[8], biv[8];
        #pragma unroll
        for (int j = 0; j < 8; j++) arv[j] = actA ? xrA[t + 64 * j] : 0.f;
        #pragma unroll
        for (int j = 0; j < 8; j++) aiv[j] = actA ? xiA[t + 64 * j] : 0.f;
        #pragma unroll
        for (int j = 0; j < 8; j++) brv[j] = actB ? xrB[t + 64 * j] : 0.f;
        #pragma unroll
        for (int j = 0; j < 8; j++) biv[j] = actB ? xiB[t + 64 * j] : 0.f;
        #pragma unroll
        for (int j = 0; j < 8; j++) { a[j] = make_float2(arv[j], aiv[j]);
                                      b[j] = make_float2(brv[j], biv[j]); }
    }

    // ---- Stage 1 (both rows): radix-8 over j2, twiddle (W^t)^h2 ----
    dft8(a); twiddle_chain(a, base1);
    dft8(b); twiddle_chain(b, base1);

    // exchange 1 store: pitch 72 (conflict-free)
    #pragma unroll
    for (int h = 0; h < 8; h++) {
        int p = h * 72 + t;
        bufAre[grp][p] = a[h].x;  bufAim[grp][p] = a[h].y;
        bufBre[grp][p] = b[h].x;  bufBim[grp][p] = b[h].y;
    }
    group_bar(grp);

    // ---- Stage 2 (both rows): radix-8 over j1, twiddle (W^(8*j0))^h1 ----
    #pragma unroll
    for (int j1 = 0; j1 < 8; j1++) {
        int p = h2s * 72 + j1 * 8 + j0;
        a[j1] = make_float2(bufAre[grp][p], bufAim[grp][p]);
        b[j1] = make_float2(bufBre[grp][p], bufBim[grp][p]);
    }
    dft8(a); twiddle_chain(a, base2);
    dft8(b); twiddle_chain(b, base2);

    group_bar(grp);   // all exchange-1 reads done before overwrite

    // exchange 2 store: pitch 68 -> banks 4*j0 + h2 + 8*h1, perfect cover
    #pragma unroll
    for (int h = 0; h < 8; h++) {
        int p = j0 * 68 + h * 8 + h2s;
        bufAre[grp][p] = a[h].x;  bufAim[grp][p] = a[h].y;
        bufBre[grp][p] = b[h].x;  bufBim[grp][p] = b[h].y;
    }
    group_bar(grp);

    // ---- Stage 3 (both rows): radix-8 over j0; output h = h0*64 + t ----
    #pragma unroll
    for (int j = 0; j < 8; j++) {
        int p = j * 68 + t;
        a[j] = make_float2(bufAre[grp][p], bufAim[grp][p]);
        b[j] = make_float2(bufBre[grp][p], bufBim[grp][p]);
    }
    dft8(a);
    dft8(b);

    if (actA) {
        float2* orow = out + (size_t)rowA * 512;
        #pragma unroll
        for (int h0 = 0; h0 < 8; h0++) orow[h0 * 64 + t] = a[h0];
    }
    if (actB) {
        float2* orow = out + (size_t)rowB * 512;
        #pragma unroll
        for (int h0 = 0; h0 < 8; h0++) orow[h0 * 64 + t] = b[h0];
    }
}

extern "C" void kernel_launch(void* const* d_in, const int* in_sizes, int n_in,
                              void* d_out, int out_size)
{
    const float* xre = (const float*)d_in[0];
    const float* xim = (const float*)d_in[1];
    const float* wre = (const float*)d_in[2];
    const float* wim = (const float*)d_in[3];
    float2* out = (float2*)d_out;

    const int nrows = in_sizes[0] / 512;            // 32768
    const int rows_per_cta = GROUPS * 2;            // 8
    const int grid = (nrows + rows_per_cta - 1) / rows_per_cta;   // 4096
    fft512_kernel<<<grid, CTA_THREADS>>>(xre, xim, wre, wim, out, nrows);
}

// round 9
// speedup vs baseline: 1.3441x; 1.3441x over previous
#include <cuda_runtime.h>

// Range_Fourier_Net: y = DFT_512(x) per row, complex, output stacked (re, im).
// Radix-8^3 FFT, exact twiddles generated from row 1 of the DFT weight matrix.
//
// R8 = R4 structure (2 rows per 64-thread group, 3 named group barriers,
// launch_bounds(256,3)) with PAIRED float2 exchange buffers: rows A and B
// undergo the same permutation, so each smem element is float2(.x=A, .y=B).
// Halves STS/LDS instruction count (64-bit ops). Pitches 72 / 66 are
// conflict-free for 64-bit accesses in every phase (verified per half-warp).

#define GROUPS 4
#define CTA_THREADS (GROUPS * 64)
#define BUF_LEN 576   // >= 7*72+63+1 = 568 and >= 7*66+63+1 = 526

__device__ __forceinline__ float2 cadd(float2 a, float2 b) {
    return make_float2(a.x + b.x, a.y + b.y);
}
__device__ __forceinline__ float2 csub(float2 a, float2 b) {
    return make_float2(a.x - b.x, a.y - b.y);
}
__device__ __forceinline__ float2 cmul(float2 a, float2 b) {
    return make_float2(fmaf(a.x, b.x, -a.y * b.y), fmaf(a.x, b.y, a.y * b.x));
}
// multiply by -i  (W8^2)
__device__ __forceinline__ float2 mul_mi(float2 a) { return make_float2(a.y, -a.x); }

// Natural-order 8-point DFT: v[h] = sum_j v_in[j] * W8^{j*h}, W8 = exp(-i*pi/4)
__device__ __forceinline__ void dft8(float2 v[8]) {
    float2 e0 = v[0], e1 = v[2], e2 = v[4], e3 = v[6];
    float2 o0 = v[1], o1 = v[3], o2 = v[5], o3 = v[7];
    float2 t0 = cadd(e0, e2), t1 = csub(e0, e2);
    float2 t2 = cadd(e1, e3), t3 = mul_mi(csub(e1, e3));
    float2 E0 = cadd(t0, t2), E2 = csub(t0, t2);
    float2 E1 = cadd(t1, t3), E3 = csub(t1, t3);
    float2 s0 = cadd(o0, o2), s1 = csub(o0, o2);
    float2 s2 = cadd(o1, o3), s3 = mul_mi(csub(o1, o3));
    float2 O0 = cadd(s0, s2), O2 = csub(s0, s2);
    float2 O1 = cadd(s1, s3), O3 = csub(s1, s3);
    const float S = 0.70710678118654752440f;
    float2 W1 = make_float2(S * (O1.x + O1.y), S * (O1.y - O1.x));
    float2 W2 = mul_mi(O2);
    float2 W3 = make_float2(S * (O3.y - O3.x), -S * (O3.x + O3.y));
    v[0] = cadd(E0, O0); v[4] = csub(E0, O0);
    v[1] = cadd(E1, W1); v[5] = csub(E1, W1);
    v[2] = cadd(E2, W2); v[6] = csub(E2, W2);
    v[3] = cadd(E3, W3); v[7] = csub(E3, W3);
}

__device__ __forceinline__ void group_bar(int grp) {
    asm volatile("bar.sync %0, 64;" :: "r"(grp + 1) : "memory");
}

// twiddle chain: v[h] *= base^h for h = 1..7
__device__ __forceinline__ void twiddle_chain(float2 v[8], float2 base) {
    float2 f = base;
    #pragma unroll
    for (int h = 1; h < 8; h++) {
        v[h] = cmul(v[h], f);
        if (h < 7) f = cmul(f, base);
    }
}

__global__ __launch_bounds__(CTA_THREADS, 3)
void fft512_kernel(const float* __restrict__ xre, const float* __restrict__ xim,
                   const float* __restrict__ wre, const float* __restrict__ wim,
                   float2* __restrict__ out, int nrows)
{
    // paired buffers: element = (rowA value, rowB value)
    __shared__ float2 bufRe[GROUPS][BUF_LEN];
    __shared__ float2 bufIm[GROUPS][BUF_LEN];

    const int tid = threadIdx.x;
    const int grp = tid >> 6;      // group within CTA
    const int t   = tid & 63;      // 0..63
    const int j0  = t & 7;
    const int h2s = t >> 3;
    const int rowA = (blockIdx.x * GROUPS + grp) * 2;
    const int rowB = rowA + 1;
    const bool actA = rowA < nrows;
    const bool actB = rowB < nrows;

    // Per-thread exact base twiddles from DFT-matrix row 1: W512^m = w[512+m]
    const float2 base1 = make_float2(__ldg(&wre[512 + t]),      __ldg(&wim[512 + t]));
    const float2 base2 = make_float2(__ldg(&wre[512 + 8 * j0]), __ldg(&wim[512 + 8 * j0]));

    // ---- front-batched loads: 32 LDGs in flight ----
    float2 a[8], b[8];
    {
        const float* xrA = xre + (size_t)rowA * 512;
        const float* xiA = xim + (size_t)rowA * 512;
        const float* xrB = xre + (size_t)rowB * 512;
        const float* xiB = xim + (size_t)rowB * 512;
        float arv[8], aiv[8], brv[8], biv[8];
        #pragma unroll
        for (int j = 0; j < 8; j++) arv[j] = actA ? xrA[t + 64 * j] : 0.f;
        #pragma unroll
        for (int j = 0; j < 8; j++) aiv[j] = actA ? xiA[t + 64 * j] : 0.f;
        #pragma unroll
        for (int j = 0; j < 8; j++) brv[j] = actB ? xrB[t + 64 * j] : 0.f;
        #pragma unroll
        for (int j = 0; j < 8; j++) biv[j] = actB ? xiB[t + 64 * j] : 0.f;
        #pragma unroll
        for (int j = 0; j < 8; j++) { a[j] = make_float2(arv[j], aiv[j]);
                                      b[j] = make_float2(brv[j], biv[j]); }
    }

    // ---- Stage 1 (both rows): radix-8 over j2, twiddle (W^t)^h2 ----
    dft8(a); twiddle_chain(a, base1);
    dft8(b); twiddle_chain(b, base1);

    // exchange 1 store: pitch 72, STS.64 (words 16h+2t: conflict-free)
    #pragma unroll
    for (int h = 0; h < 8; h++) {
        int p = h * 72 + t;
        bufRe[grp][p] = make_float2(a[h].x, b[h].x);
        bufIm[grp][p] = make_float2(a[h].y, b[h].y);
    }
    group_bar(grp);

    // ---- Stage 2 (both rows): radix-8 over j1, twiddle (W^(8*j0))^h1 ----
    #pragma unroll
    for (int j1 = 0; j1 < 8; j1++) {
        int p = h2s * 72 + j1 * 8 + j0;
        float2 re = bufRe[grp][p];
        float2 im = bufIm[grp][p];
        a[j1] = make_float2(re.x, im.x);
        b[j1] = make_float2(re.y, im.y);
    }
    dft8(a); twiddle_chain(a, base2);
    dft8(b); twiddle_chain(b, base2);

    group_bar(grp);   // all exchange-1 reads done before overwrite

    // exchange 2 store: pitch 66 (words 4*j0+16h+2h2: conflict-free for .64)
    #pragma unroll
    for (int h = 0; h < 8; h++) {
        int p = j0 * 66 + h * 8 + h2s;
        bufRe[grp][p] = make_float2(a[h].x, b[h].x);
        bufIm[grp][p] = make_float2(a[h].y, b[h].y);
    }
    group_bar(grp);

    // ---- Stage 3 (both rows): radix-8 over j0; output h = h0*64 + t ----
    #pragma unroll
    for (int j = 0; j < 8; j++) {
        int p = j * 66 + t;
        float2 re = bufRe[grp][p];
        float2 im = bufIm[grp][p];
        a[j] = make_float2(re.x, im.x);
        b[j] = make_float2(re.y, im.y);
    }
    dft8(a);
    dft8(b);

    if (actA) {
        float2* orow = out + (size_t)rowA * 512;
        #pragma unroll
        for (int h0 = 0; h0 < 8; h0++) orow[h0 * 64 + t] = a[h0];
    }
    if (actB) {
        float2* orow = out + (size_t)rowB * 512;
        #pragma unroll
        for (int h0 = 0; h0 < 8; h0++) orow[h0 * 64 + t] = b[h0];
    }
}

extern "C" void kernel_launch(void* const* d_in, const int* in_sizes, int n_in,
                              void* d_out, int out_size)
{
    const float* xre = (const float*)d_in[0];
    const float* xim = (const float*)d_in[1];
    const float* wre = (const float*)d_in[2];
    const float* wim = (const float*)d_in[3];
    float2* out = (float2*)d_out;

    const int nrows = in_sizes[0] / 512;            // 32768
    const int rows_per_cta = GROUPS * 2;            // 8
    const int grid = (nrows + rows_per_cta - 1) / rows_per_cta;   // 4096
    fft512_kernel<<<grid, CTA_THREADS>>>(xre, xim, wre, wim, out, nrows);
}